// round 1
// baseline (speedup 1.0000x reference)
#include <cuda_runtime.h>
#include <math.h>

// Problem constants
#define B_   4
#define L_   2048
#define E_   1024
#define H_   16
#define DK_  64
#define MTOK (B_ * L_)          // 8192 token rows
#define QKV_N (3 * H_ * DK_)    // 3072
#define HD_  (H_ * DK_)         // 1024

// Scratch (allocation-free rule: __device__ globals)
__device__ float g_qkv[(size_t)MTOK * QKV_N];  // [8192, 3072]
__device__ float g_att[(size_t)MTOK * HD_];    // [8192, 1024]

// ---------------------------------------------------------------------------
// SGEMM with fused bias: C[M,N] = A[M,K] @ B[K,N] + bias[N]
// 128x128 block tile, BK=8, 256 threads, 8x8 register microtile.
// Assumes M%128==0, N%128==0, K%8==0 (true for all calls here).
// ---------------------------------------------------------------------------
__global__ __launch_bounds__(256) void sgemm_bias_kernel(
    const float* __restrict__ A, const float* __restrict__ B,
    const float* __restrict__ bias, float* __restrict__ C,
    int M, int N, int K)
{
    __shared__ float As[8][128];   // stored transposed: As[k][m]
    __shared__ float Bs[8][128];   // Bs[k][n]

    const int tid  = threadIdx.x;
    const int brow = blockIdx.y * 128;
    const int bcol = blockIdx.x * 128;

    // A tile load mapping: 128 rows x 8 cols = 256 float4
    const int aRow = tid >> 1;          // 0..127
    const int aCol = (tid & 1) << 2;    // 0 or 4
    // B tile load mapping: 8 rows x 128 cols = 256 float4
    const int bRow = tid >> 5;          // 0..7
    const int bCol = (tid & 31) << 2;   // 0..124

    const int ty = tid >> 4;            // 0..15 -> C rows ty*8..+7
    const int tx = tid & 15;            // 0..15 -> C cols tx*8..+7

    float acc[8][8];
    #pragma unroll
    for (int i = 0; i < 8; ++i)
        #pragma unroll
        for (int j = 0; j < 8; ++j) acc[i][j] = 0.f;

    const float* Ap = A + (size_t)(brow + aRow) * K + aCol;
    const float* Bp = B + (size_t)bRow * N + bcol + bCol;

    for (int k0 = 0; k0 < K; k0 += 8) {
        float4 av = *(const float4*)(Ap + k0);
        As[aCol + 0][aRow] = av.x;
        As[aCol + 1][aRow] = av.y;
        As[aCol + 2][aRow] = av.z;
        As[aCol + 3][aRow] = av.w;
        float4 bv = *(const float4*)(Bp + (size_t)k0 * N);
        *(float4*)&Bs[bRow][bCol] = bv;
        __syncthreads();

        #pragma unroll
        for (int kk = 0; kk < 8; ++kk) {
            float ra[8], rb[8];
            *(float4*)&ra[0] = *(const float4*)&As[kk][ty * 8];
            *(float4*)&ra[4] = *(const float4*)&As[kk][ty * 8 + 4];
            *(float4*)&rb[0] = *(const float4*)&Bs[kk][tx * 8];
            *(float4*)&rb[4] = *(const float4*)&Bs[kk][tx * 8 + 4];
            #pragma unroll
            for (int i = 0; i < 8; ++i)
                #pragma unroll
                for (int j = 0; j < 8; ++j)
                    acc[i][j] = fmaf(ra[i], rb[j], acc[i][j]);
        }
        __syncthreads();
    }

    #pragma unroll
    for (int i = 0; i < 8; ++i) {
        const size_t crow = (size_t)(brow + ty * 8 + i) * N + bcol + tx * 8;
        #pragma unroll
        for (int j4 = 0; j4 < 8; j4 += 4) {
            float4 v;
            v.x = acc[i][j4 + 0] + __ldg(&bias[bcol + tx * 8 + j4 + 0]);
            v.y = acc[i][j4 + 1] + __ldg(&bias[bcol + tx * 8 + j4 + 1]);
            v.z = acc[i][j4 + 2] + __ldg(&bias[bcol + tx * 8 + j4 + 2]);
            v.w = acc[i][j4 + 3] + __ldg(&bias[bcol + tx * 8 + j4 + 3]);
            *(float4*)(C + crow + j4) = v;
        }
    }
}

// ---------------------------------------------------------------------------
// Flash-attention style kernel (fp32, online softmax).
// Grid: (L/64, H, B). Block: 256 threads.
// Per block: 64 query rows of one (b,h). Loops over 32 key chunks of 64.
// S = Q K^T and O += P V computed as smem GEMMs with 4x4 microtiles.
// QKV layout in g_qkv: row (b*L + l), col h*192 + {0..63 Q, 64..127 K, 128..191 V}
// ---------------------------------------------------------------------------
#define ATT_PITCH 68     // row pad, keeps float4 alignment, kills bank conflicts
#define ATT_SMEM_BYTES (4 * 64 * ATT_PITCH * (int)sizeof(float))   // 69632

__global__ __launch_bounds__(256) void attn_kernel(
    const float* __restrict__ qkv, float* __restrict__ att)
{
    extern __shared__ float sm[];
    float* Qt = sm;                        // [d][q]  64 x 68
    float* Kt = Qt + 64 * ATT_PITCH;       // [d][j]  64 x 68
    float* Vs = Kt + 64 * ATT_PITCH;       // [j][d]  64 x 68
    float* Pt = Vs + 64 * ATT_PITCH;       // [j][q]  64 x 68

    const int b  = blockIdx.z;
    const int h  = blockIdx.y;
    const int q0 = blockIdx.x * 64;
    const int tid = threadIdx.x;
    const int ty = tid >> 4;   // 0..15 -> q rows ty*4..+3 (and O rows)
    const int tx = tid & 15;   // 0..15 -> key cols / d cols tx*4..+3

    const size_t base = ((size_t)b * L_) * QKV_N + (size_t)h * (3 * DK_);

    // Load Q tile (transposed into Qt[d][q])
    for (int t = tid; t < 64 * 16; t += 256) {
        const int q  = t >> 4;
        const int d4 = (t & 15) << 2;
        float4 v = *(const float4*)(qkv + base + (size_t)(q0 + q) * QKV_N + d4);
        Qt[(d4 + 0) * ATT_PITCH + q] = v.x;
        Qt[(d4 + 1) * ATT_PITCH + q] = v.y;
        Qt[(d4 + 2) * ATT_PITCH + q] = v.z;
        Qt[(d4 + 3) * ATT_PITCH + q] = v.w;
    }

    float o[4][4];
    float m_i[4], l_i[4];
    #pragma unroll
    for (int i = 0; i < 4; ++i) {
        m_i[i] = -INFINITY; l_i[i] = 0.f;
        #pragma unroll
        for (int j = 0; j < 4; ++j) o[i][j] = 0.f;
    }
    const float scale = 0.125f;  // 1/sqrt(64)

    for (int kc = 0; kc < L_; kc += 64) {
        __syncthreads();   // prev PV done (and Q tile visible on 1st iter)

        // Load K chunk (transposed) and V chunk (natural)
        for (int t = tid; t < 64 * 16; t += 256) {
            const int j  = t >> 4;
            const int d4 = (t & 15) << 2;
            const float* rp = qkv + base + (size_t)(kc + j) * QKV_N;
            float4 kv = *(const float4*)(rp + DK_ + d4);
            Kt[(d4 + 0) * ATT_PITCH + j] = kv.x;
            Kt[(d4 + 1) * ATT_PITCH + j] = kv.y;
            Kt[(d4 + 2) * ATT_PITCH + j] = kv.z;
            Kt[(d4 + 3) * ATT_PITCH + j] = kv.w;
            float4 vv = *(const float4*)(rp + 2 * DK_ + d4);
            *(float4*)&Vs[j * ATT_PITCH + d4] = vv;
        }
        __syncthreads();

        // S = Q K^T  (64x64x64 tile GEMM, 4x4 microtile)
        float s[4][4];
        #pragma unroll
        for (int i = 0; i < 4; ++i)
            #pragma unroll
            for (int j = 0; j < 4; ++j) s[i][j] = 0.f;

        #pragma unroll 4
        for (int d = 0; d < 64; ++d) {
            const float4 qa = *(const float4*)(Qt + d * ATT_PITCH + ty * 4);
            const float4 kb = *(const float4*)(Kt + d * ATT_PITCH + tx * 4);
            const float qv[4] = {qa.x, qa.y, qa.z, qa.w};
            const float kv[4] = {kb.x, kb.y, kb.z, kb.w};
            #pragma unroll
            for (int i = 0; i < 4; ++i)
                #pragma unroll
                for (int j = 0; j < 4; ++j)
                    s[i][j] = fmaf(qv[i], kv[j], s[i][j]);
        }

        // Online softmax (row groups = 16 consecutive lanes, shfl width 16)
        #pragma unroll
        for (int i = 0; i < 4; ++i) {
            float mloc = -INFINITY;
            #pragma unroll
            for (int j = 0; j < 4; ++j) {
                s[i][j] *= scale;
                mloc = fmaxf(mloc, s[i][j]);
            }
            #pragma unroll
            for (int off = 8; off > 0; off >>= 1)
                mloc = fmaxf(mloc, __shfl_xor_sync(0xffffffffu, mloc, off, 16));

            const float mnew = fmaxf(m_i[i], mloc);
            const float corr = __expf(m_i[i] - mnew);
            m_i[i] = mnew;

            float lsum = 0.f;
            #pragma unroll
            for (int j = 0; j < 4; ++j) {
                const float p = __expf(s[i][j] - mnew);
                s[i][j] = p;
                lsum += p;
            }
            #pragma unroll
            for (int off = 8; off > 0; off >>= 1)
                lsum += __shfl_xor_sync(0xffffffffu, lsum, off, 16);

            l_i[i] = l_i[i] * corr + lsum;
            #pragma unroll
            for (int j = 0; j < 4; ++j) o[i][j] *= corr;
        }

        // Write P transposed: Pt[j][q]
        #pragma unroll
        for (int j = 0; j < 4; ++j)
            #pragma unroll
            for (int i = 0; i < 4; ++i)
                Pt[(tx * 4 + j) * ATT_PITCH + ty * 4 + i] = s[i][j];
        __syncthreads();

        // O += P V (64x64x64 tile GEMM)
        #pragma unroll 4
        for (int j = 0; j < 64; ++j) {
            const float4 pa = *(const float4*)(Pt + j * ATT_PITCH + ty * 4);
            const float4 vb = *(const float4*)(Vs + j * ATT_PITCH + tx * 4);
            const float pv[4] = {pa.x, pa.y, pa.z, pa.w};
            const float vv[4] = {vb.x, vb.y, vb.z, vb.w};
            #pragma unroll
            for (int i = 0; i < 4; ++i)
                #pragma unroll
                for (int d = 0; d < 4; ++d)
                    o[i][d] = fmaf(pv[i], vv[d], o[i][d]);
        }
    }

    // Normalize and write: att[b, l, h*64 + d]
    #pragma unroll
    for (int i = 0; i < 4; ++i) {
        const float inv = 1.f / l_i[i];
        float4 v;
        v.x = o[i][0] * inv; v.y = o[i][1] * inv;
        v.z = o[i][2] * inv; v.w = o[i][3] * inv;
        const size_t idx = ((size_t)b * L_ + q0 + ty * 4 + i) * HD_
                         + (size_t)h * DK_ + tx * 4;
        *(float4*)(att + idx) = v;
    }
}

// ---------------------------------------------------------------------------
// Launch
// ---------------------------------------------------------------------------
extern "C" void kernel_launch(void* const* d_in, const int* in_sizes, int n_in,
                              void* d_out, int out_size)
{
    const float* X    = (const float*)d_in[0];   // [4,2048,1024]
    const float* Wqkv = (const float*)d_in[1];   // [1024,3072]
    const float* bqkv = (const float*)d_in[2];   // [3072]
    const float* Wfc  = (const float*)d_in[3];   // [1024,1024]
    const float* bfc  = (const float*)d_in[4];   // [1024]
    float* out = (float*)d_out;                  // [4,2048,1024]

    float *qkv = nullptr, *att = nullptr;
    cudaGetSymbolAddress((void**)&qkv, g_qkv);
    cudaGetSymbolAddress((void**)&att, g_att);

    cudaFuncSetAttribute(attn_kernel,
                         cudaFuncAttributeMaxDynamicSharedMemorySize,
                         ATT_SMEM_BYTES);

    // 1) QKV = X @ Wqkv + bqkv     [8192, 3072]
    sgemm_bias_kernel<<<dim3(QKV_N / 128, MTOK / 128), 256>>>(
        X, Wqkv, bqkv, qkv, MTOK, QKV_N, E_);

    // 2) attention                 [8192, 1024]
    attn_kernel<<<dim3(L_ / 64, H_, B_), 256, ATT_SMEM_BYTES>>>(qkv, att);

    // 3) out = att @ Wfc + bfc     [8192, 1024]
    sgemm_bias_kernel<<<dim3(HD_ / 128, MTOK / 128), 256>>>(
        att, Wfc, bfc, out, MTOK, HD_, E_);
}